// round 16
// baseline (speedup 1.0000x reference)
#include <cuda_runtime.h>
#include <cstdint>

#define NN 100
#define DD 128
#define CH 512
#define NEG_INF __int_as_float(0xff800000)

// scratch per batch, n-major [100][132]: K@0 V@13200 P@26400 Q@39600
#define OFF_K 0
#define OFF_V 13200
#define OFF_P 26400
#define OFF_Q 39600
#define TBLK  52800

struct Args { const void* p[10]; long sz[10]; int n; int batch; };

__device__ float g_scr[(size_t)CH * TBLK];   // ~108MB, zero-init
__device__ int g_psel, g_klen, g_ok, g_enc, g_widx[5];

// ---------------- f32x2 helpers ----------------
__device__ __forceinline__ void ffma2(unsigned long long &d, unsigned long long a, unsigned long long b){
    asm("fma.rn.f32x2 %0, %1, %2, %0;" : "+l"(d) : "l"(a), "l"(b));
}
__device__ __forceinline__ unsigned long long dup2(float x){
    unsigned long long r; asm("mov.b64 %0, {%1, %1};" : "=l"(r) : "f"(x)); return r;
}
__device__ __forceinline__ void unpack2(unsigned long long v, float &lo, float &hi){
    asm("mov.b64 {%0, %1}, %2;" : "=f"(lo), "=f"(hi) : "l"(v));
}

// =====================================================================
// prep: device-side role detection by content. (proven)
// =====================================================================
__global__ void prep_kernel(Args a)
{
    if (threadIdx.x != 0) return;
    int ok = 1;

    int encIdx = 0; long mxs = -1;
    for (int i = 0; i < a.n; i++) if (a.sz[i] > mxs){ mxs = a.sz[i]; encIdx = i; }
    const long want = (long)a.batch * NN * DD;
    long scale = 1;
    if      (mxs == want)     scale = 1;
    else if (mxs == want * 4) scale = 4;
    else ok = 0;

    int psel = -1;
    for (int i = 0; i < a.n; i++){
        if (a.sz[i] / scale < 64) continue;
        const int* q = (const int*)a.p[i];
        bool good = true; int mn = 1 << 30, mxv = -1;
        for (int k = 0; k < 64; k++){
            const int v = q[k];
            if (v < 0 || v >= NN){ good = false; break; }
            mn = v < mn ? v : mn; mxv = v > mxv ? v : mxv;
        }
        if (good && mxv > mn){ psel = i; break; }
    }
    int klen = 10;
    if (psel >= 0 && a.batch > 0){
        const long kl = (a.sz[psel] / scale) / a.batch;
        if (kl >= 1 && kl <= NN) klen = (int)kl; else ok = 0;
    } else ok = 0;

    int prob = -1;
    for (int i = 0; i < a.n; i++){
        if (i == encIdx || i == psel) continue;
        if (a.sz[i] / scale == (long)DD * DD) continue;
        const float* f = (const float*)a.p[i];
        bool good = true;
        for (int k = 0; k < 64; k++){
            const float v = f[k];
            if (!(v > 0.f && v < 1.f)){ good = false; break; }
        }
        if (good){ prob = i; break; }
    }

    int w[10]; int nw = 0;
    for (int i = 0; i < a.n; i++)
        if (a.sz[i] / scale == (long)DD * DD && nw < 10) w[nw++] = i;
    if (nw != 5){ ok = 0; w[0]=2; w[1]=3; w[2]=4; w[3]=5; w[4]=6; }

    const bool dict = (prob < 0) ? true : (prob < encIdx);
    // roles: 0=Wq_first 1=Wq_last 2=Wk 3=Wv 4=Wcomb
    if (dict){ g_widx[0]=w[0]; g_widx[1]=w[1]; g_widx[2]=w[2]; g_widx[3]=w[3]; g_widx[4]=w[4]; }
    else     { g_widx[0]=w[2]; g_widx[1]=w[3]; g_widx[2]=w[1]; g_widx[3]=w[4]; g_widx[4]=w[0]; }

    g_psel = psel; g_klen = klen; g_enc = encIdx; g_ok = ok;
}

__global__ void prefill_kernel(Args a, float* __restrict__ out)
{
    const int b = blockIdx.x, tid = threadIdx.x;
    for (int j = tid; j < NN; j += blockDim.x) out[b*NN + j] = 1.0f;
    const int psel = g_psel, klen = g_klen;
    if (psel >= 0 && tid < klen){
        const int* pre = (const int*)a.p[psel];
        int p = pre[b*klen + tid];
        out[b*NN + tid] = (float)((p >= 0 && p < NN) ? p : 0);
    }
}

// =====================================================================
// gemm: grid (chunk, 4); 256 threads; f32x2 core; ALL outputs n-major. (proven)
// =====================================================================
__global__ __launch_bounds__(256, 2) void gemm_kernel(Args a, int c0)
{
    if (!g_ok) return;
    __shared__ __align__(16) float Es[32*102 + 16];
    __shared__ __align__(16) float Ws[32*132];
    __shared__ __align__(16) float q1s[128];

    const int bb = blockIdx.x, m = blockIdx.y;
    const int b = c0 + bb;
    const int tid = threadIdx.x;
    const int tx = tid & 31;
    const int ty = tid >> 5;

    const int role = (m==0) ? 2 : (m==1) ? 1 : (m==2) ? 3 : 4;
    const float* W   = (const float*)a.p[g_widx[role]];
    const float* enc = (const float*)a.p[g_enc];
    const float* Eb  = enc + (size_t)b * (NN*DD);
    const int klen = g_klen;

    if (m == 1 && tid < 128){
        const int* pre = (const int*)a.p[g_psel];
        int last = pre[b*klen + (klen-1)];
        last = (last >= 0 && last < NN) ? last : 0;
        const float* er = Eb + last*DD;
        const float* Wqf = (const float*)a.p[g_widx[0]];
        float s = 0.f;
        for (int d = 0; d < DD; d++) s += er[d] * Wqf[d*DD + tid];
        q1s[tid] = s;
    }

    unsigned long long acc[7][4];
    #pragma unroll
    for (int k = 0; k < 7; k++){ acc[k][0]=0ull; acc[k][1]=0ull; acc[k][2]=0ull; acc[k][3]=0ull; }

    for (int dch = 0; dch < 4; dch++){
        const int d0 = dch * 32;
        __syncthreads();
        for (int e = tid; e < 3200; e += 256){
            const int n = e >> 5, dd = e & 31;
            Es[dd*102 + n] = Eb[n*DD + d0 + dd];
        }
        if (m < 3){
            for (int e = tid; e < 4096; e += 256){
                const int dd = e >> 7, c = e & 127;
                Ws[dd*132 + c] = W[(d0+dd)*DD + c];
            }
        } else {
            for (int e = tid; e < 4096; e += 256){
                const int c = e >> 5, dd = e & 31;
                Ws[dd*132 + c] = W[c*DD + d0 + dd];
            }
        }
        __syncthreads();

        #pragma unroll 4
        for (int dd = 0; dd < 32; dd++){
            const float4 w4 = *(const float4*)(Ws + dd*132 + 4*tx);
            const unsigned long long w0 = dup2(w4.x), w1 = dup2(w4.y),
                                     w2 = dup2(w4.z), w3 = dup2(w4.w);
            const float* er = Es + dd*102 + 2*ty;
            #pragma unroll
            for (int k = 0; k < 7; k++){
                const unsigned long long e2 = *(const unsigned long long*)(er + 16*k);
                ffma2(acc[k][0], e2, w0);
                ffma2(acc[k][1], e2, w1);
                ffma2(acc[k][2], e2, w2);
                ffma2(acc[k][3], e2, w3);
            }
        }
    }
    __syncthreads();

    float* dst = g_scr + (size_t)bb * TBLK
               + ((m==0) ? OFF_K : (m==1) ? OFF_Q : (m==2) ? OFF_V : OFF_P);
    float4 q1v = make_float4(0.f,0.f,0.f,0.f);
    if (m == 1) q1v = *(const float4*)(q1s + 4*tx);

    #pragma unroll
    for (int k = 0; k < 7; k++){
        const int n0 = 2*(ty + 8*k);
        if (n0 >= NN) continue;
        const int n1 = n0 + 1;
        float lo0,hi0,lo1,hi1,lo2,hi2,lo3,hi3;
        unpack2(acc[k][0], lo0, hi0);
        unpack2(acc[k][1], lo1, hi1);
        unpack2(acc[k][2], lo2, hi2);
        unpack2(acc[k][3], lo3, hi3);
        *(float4*)(dst + n0*132 + 4*tx) = make_float4(lo0+q1v.x, lo1+q1v.y, lo2+q1v.z, lo3+q1v.w);
        *(float4*)(dst + n1*132 + 4*tx) = make_float4(hi0+q1v.x, hi1+q1v.y, hi2+q1v.z, hi3+q1v.w);
    }
}

// =====================================================================
// decode_warp: ONE WARP = ONE BATCH. No barriers; tables stream from L2.
// smem per CTA (1 warp): att[800] + mh[128] + idxs[104] ints.
// =====================================================================
__global__ __launch_bounds__(32, 16) void decode_kernel(Args a, int c0, float* __restrict__ out)
{
    if (!g_ok || g_psel < 0) return;
    __shared__ __align__(16) float attw[800];
    __shared__ __align__(16) float mhb[128];
    __shared__ __align__(16) int   idxs[104];

    const int bl = blockIdx.x;            // local chunk batch
    const int bg = c0 + bl;               // global batch
    const int lane = threadIdx.x;
    const int klen = g_klen;
    const int* pre = (const int*)a.p[g_psel];

    const float* __restrict__ scrK = g_scr + (size_t)bl * TBLK + OFF_K;
    const float* __restrict__ scrV = g_scr + (size_t)bl * TBLK + OFF_V;
    const float* __restrict__ scrP = g_scr + (size_t)bl * TBLK + OFF_P;
    const float* __restrict__ scrQ = g_scr + (size_t)bl * TBLK + OFF_Q;

    // ---- init: visited scratch in attw, emit prefix, build active list ----
    {
        int* vis = (int*)attw;
        #pragma unroll
        for (int k = 0; k < 4; k++){
            const int n = lane + 32*k;
            if (n < NN) vis[n] = 0;
        }
        __syncwarp();
        for (int k = lane; k < klen; k += 32){
            int p = pre[bg*klen + k];
            p = (p >= 0 && p < NN) ? p : 0;
            vis[p] = 1;
            out[bg*NN + k] = (float)p;
        }
        __syncwarp();
        if (lane == 0){
            int m = 0;
            for (int n = 0; n < NN; n++) if (!vis[n]) idxs[m++] = n;
        }
        __syncwarp();
    }
    int last0 = pre[bg*klen + (klen-1)];
    int cur = (last0 >= 0 && last0 < NN) ? last0 : 0;

    const int steps = NN - klen;
    for (int step = 0; step < steps; step++){
        const int act = steps - step;

        // ---- Phase A: att[h][j] = exp(q_h.K[idx[j]]_h / 4); h = lane&7 fixed ----
        {
            const int h = lane & 7;
            const float* Qrow = scrQ + cur*132 + h*16;
            const ulonglong2 q0 = *(const ulonglong2*)(Qrow);
            const ulonglong2 q1 = *(const ulonglong2*)(Qrow + 4);
            const ulonglong2 q2 = *(const ulonglong2*)(Qrow + 8);
            const ulonglong2 q3 = *(const ulonglong2*)(Qrow + 12);
            for (int p = lane; p < 8*act; p += 32){
                const int j = p >> 3;
                const float* Krow = scrK + idxs[j]*132 + h*16;
                const ulonglong2 k0 = *(const ulonglong2*)(Krow);
                const ulonglong2 k1 = *(const ulonglong2*)(Krow + 4);
                const ulonglong2 k2 = *(const ulonglong2*)(Krow + 8);
                const ulonglong2 k3 = *(const ulonglong2*)(Krow + 12);
                unsigned long long a0 = 0ull, a1 = 0ull;
                ffma2(a0, k0.x, q0.x); ffma2(a1, k0.y, q0.y);
                ffma2(a0, k1.x, q1.x); ffma2(a1, k1.y, q1.y);
                ffma2(a0, k2.x, q2.x); ffma2(a1, k2.y, q2.y);
                ffma2(a0, k3.x, q3.x); ffma2(a1, k3.y, q3.y);
                float s0,s1,s2,s3;
                unpack2(a0, s0, s1);
                unpack2(a1, s2, s3);
                attw[h*100 + j] = expf(((s0+s1) + (s2+s3)) * 0.25f);
            }
        }
        __syncwarp();

        // ---- Phase C: lane owns c-quad 4*lane..4*lane+3 (head hq = lane>>2) ----
        {
            const int hq = lane >> 2;
            const float* ar = attw + hq*100;
            const float* vbase = scrV + 4*lane;
            unsigned long long av0 = 0ull, av1 = 0ull;
            float accz = 0.f;
            #pragma unroll 4
            for (int j = 0; j < act; j++){
                const float wgt = ar[j];                         // LDS (broadcast x4)
                const ulonglong2 v2 = *(const ulonglong2*)(vbase + idxs[j]*132);  // LDG.128
                const unsigned long long wd = dup2(wgt);
                ffma2(av0, wd, v2.x);
                ffma2(av1, wd, v2.y);
                accz += wgt;
            }
            const float rz = 1.0f / accz;
            float m0,m1,m2,m3;
            unpack2(av0, m0, m1);
            unpack2(av1, m2, m3);
            *(float4*)(mhb + 4*lane) = make_float4(m0*rz, m1*rz, m2*rz, m3*rz);
        }
        __syncwarp();

        // ---- Phase DE: sc = mh.P[node] per active j; warp argmax (node tie-break) ----
        float best = NEG_INF; int bn = 1000 + lane, bj = 0;
        #pragma unroll
        for (int k = 0; k < 3; k++){
            const int j = lane + 32*k;
            if (j < act){
                const int node = idxs[j];
                const float* Prow = scrP + node*132;
                unsigned long long a0 = 0ull, a1 = 0ull;
                #pragma unroll 8
                for (int q = 0; q < 32; q++){
                    const ulonglong2 pq = *(const ulonglong2*)(Prow + 4*q);  // LDG
                    const ulonglong2 mq = *(const ulonglong2*)(mhb + 4*q);   // LDS
                    ffma2(a0, mq.x, pq.x);
                    ffma2(a1, mq.y, pq.y);
                }
                float s0,s1,s2,s3;
                unpack2(a0, s0, s1);
                unpack2(a1, s2, s3);
                const float v = (s0+s1) + (s2+s3);   // tanh & 1/sqrt(d) monotone: skip
                if (v > best || (v == best && node < bn)){ best = v; bn = node; bj = j; }
            }
        }
        #pragma unroll
        for (int o = 16; o; o >>= 1){
            const float ov = __shfl_xor_sync(0xffffffffu, best, o);
            const int   on = __shfl_xor_sync(0xffffffffu, bn,   o);
            const int   oj = __shfl_xor_sync(0xffffffffu, bj,   o);
            if (ov > best || (ov == best && on < bn)){ best = ov; bn = on; bj = oj; }
        }
        // all lanes agree on winner
        if (lane == 0){
            idxs[bj] = idxs[act-1];
            out[bg*NN + klen + step] = (float)bn;
        }
        cur = bn;
        __syncwarp();
    }
}

// =====================================================================
extern "C" void kernel_launch(void* const* d_in, const int* in_sizes, int n_in,
                              void* d_out, int out_size)
{
    Args a;
    for (int i = 0; i < 10; i++){
        a.p[i]  = (i < n_in) ? d_in[i] : d_in[0];
        a.sz[i] = (i < n_in) ? (long)in_sizes[i] : 0;
    }
    a.n = (n_in < 10) ? n_in : 10;
    a.batch = out_size / NN;
    if (a.batch < 1) a.batch = 1;
    float* out = (float*)d_out;

    prep_kernel<<<1, 32>>>(a);
    prefill_kernel<<<a.batch, 128>>>(a, out);

    for (int c0 = 0; c0 < a.batch; c0 += CH){
        const int cb = (a.batch - c0 < CH) ? (a.batch - c0) : CH;
        dim3 g(cb, 4);
        gemm_kernel<<<g, 256>>>(a, c0);
        decode_kernel<<<cb, 32>>>(a, c0, out);    // one warp per batch
    }
}

// round 17
// speedup vs baseline: 1.3952x; 1.3952x over previous
#include <cuda_runtime.h>
#include <cstdint>

#define NN 100
#define DD 128
#define CH 512
#define NEG_INF __int_as_float(0xff800000)

// scratch per batch, n-major [100][132]: K@0 V@13200 P@26400 Q@39600
#define OFF_K 0
#define OFF_V 13200
#define OFF_P 26400
#define OFF_Q 39600
#define TBLK  52800

struct Args { const void* p[10]; long sz[10]; int n; int batch; };

__device__ float g_scr[(size_t)CH * TBLK];   // ~108MB, zero-init
__device__ int g_psel, g_klen, g_ok, g_enc, g_widx[5];

// ---------------- f32x2 helpers ----------------
__device__ __forceinline__ void ffma2(unsigned long long &d, unsigned long long a, unsigned long long b){
    asm("fma.rn.f32x2 %0, %1, %2, %0;" : "+l"(d) : "l"(a), "l"(b));
}
__device__ __forceinline__ unsigned long long dup2(float x){
    unsigned long long r; asm("mov.b64 %0, {%1, %1};" : "=l"(r) : "f"(x)); return r;
}
__device__ __forceinline__ void unpack2(unsigned long long v, float &lo, float &hi){
    asm("mov.b64 {%0, %1}, %2;" : "=f"(lo), "=f"(hi) : "l"(v));
}

// =====================================================================
// prep: device-side role detection by content. (proven)
// =====================================================================
__global__ void prep_kernel(Args a)
{
    if (threadIdx.x != 0) return;
    int ok = 1;

    int encIdx = 0; long mxs = -1;
    for (int i = 0; i < a.n; i++) if (a.sz[i] > mxs){ mxs = a.sz[i]; encIdx = i; }
    const long want = (long)a.batch * NN * DD;
    long scale = 1;
    if      (mxs == want)     scale = 1;
    else if (mxs == want * 4) scale = 4;
    else ok = 0;

    int psel = -1;
    for (int i = 0; i < a.n; i++){
        if (a.sz[i] / scale < 64) continue;
        const int* q = (const int*)a.p[i];
        bool good = true; int mn = 1 << 30, mxv = -1;
        for (int k = 0; k < 64; k++){
            const int v = q[k];
            if (v < 0 || v >= NN){ good = false; break; }
            mn = v < mn ? v : mn; mxv = v > mxv ? v : mxv;
        }
        if (good && mxv > mn){ psel = i; break; }
    }
    int klen = 10;
    if (psel >= 0 && a.batch > 0){
        const long kl = (a.sz[psel] / scale) / a.batch;
        if (kl >= 1 && kl <= NN) klen = (int)kl; else ok = 0;
    } else ok = 0;

    int prob = -1;
    for (int i = 0; i < a.n; i++){
        if (i == encIdx || i == psel) continue;
        if (a.sz[i] / scale == (long)DD * DD) continue;
        const float* f = (const float*)a.p[i];
        bool good = true;
        for (int k = 0; k < 64; k++){
            const float v = f[k];
            if (!(v > 0.f && v < 1.f)){ good = false; break; }
        }
        if (good){ prob = i; break; }
    }

    int w[10]; int nw = 0;
    for (int i = 0; i < a.n; i++)
        if (a.sz[i] / scale == (long)DD * DD && nw < 10) w[nw++] = i;
    if (nw != 5){ ok = 0; w[0]=2; w[1]=3; w[2]=4; w[3]=5; w[4]=6; }

    const bool dict = (prob < 0) ? true : (prob < encIdx);
    // roles: 0=Wq_first 1=Wq_last 2=Wk 3=Wv 4=Wcomb
    if (dict){ g_widx[0]=w[0]; g_widx[1]=w[1]; g_widx[2]=w[2]; g_widx[3]=w[3]; g_widx[4]=w[4]; }
    else     { g_widx[0]=w[2]; g_widx[1]=w[3]; g_widx[2]=w[1]; g_widx[3]=w[4]; g_widx[4]=w[0]; }

    g_psel = psel; g_klen = klen; g_enc = encIdx; g_ok = ok;
}

__global__ void prefill_kernel(Args a, float* __restrict__ out)
{
    const int b = blockIdx.x, tid = threadIdx.x;
    for (int j = tid; j < NN; j += blockDim.x) out[b*NN + j] = 1.0f;
    const int psel = g_psel, klen = g_klen;
    if (psel >= 0 && tid < klen){
        const int* pre = (const int*)a.p[psel];
        int p = pre[b*klen + tid];
        out[b*NN + tid] = (float)((p >= 0 && p < NN) ? p : 0);
    }
}

// =====================================================================
// gemm: grid (chunk, 4); 256 threads; f32x2 core; ALL outputs n-major. (proven)
// =====================================================================
__global__ __launch_bounds__(256, 2) void gemm_kernel(Args a, int c0)
{
    if (!g_ok) return;
    __shared__ __align__(16) float Es[32*102 + 16];
    __shared__ __align__(16) float Ws[32*132];
    __shared__ __align__(16) float q1s[128];

    const int bb = blockIdx.x, m = blockIdx.y;
    const int b = c0 + bb;
    const int tid = threadIdx.x;
    const int tx = tid & 31;
    const int ty = tid >> 5;

    const int role = (m==0) ? 2 : (m==1) ? 1 : (m==2) ? 3 : 4;
    const float* W   = (const float*)a.p[g_widx[role]];
    const float* enc = (const float*)a.p[g_enc];
    const float* Eb  = enc + (size_t)b * (NN*DD);
    const int klen = g_klen;

    if (m == 1 && tid < 128){
        const int* pre = (const int*)a.p[g_psel];
        int last = pre[b*klen + (klen-1)];
        last = (last >= 0 && last < NN) ? last : 0;
        const float* er = Eb + last*DD;
        const float* Wqf = (const float*)a.p[g_widx[0]];
        float s = 0.f;
        for (int d = 0; d < DD; d++) s += er[d] * Wqf[d*DD + tid];
        q1s[tid] = s;
    }

    unsigned long long acc[7][4];
    #pragma unroll
    for (int k = 0; k < 7; k++){ acc[k][0]=0ull; acc[k][1]=0ull; acc[k][2]=0ull; acc[k][3]=0ull; }

    for (int dch = 0; dch < 4; dch++){
        const int d0 = dch * 32;
        __syncthreads();
        for (int e = tid; e < 3200; e += 256){
            const int n = e >> 5, dd = e & 31;
            Es[dd*102 + n] = Eb[n*DD + d0 + dd];
        }
        if (m < 3){
            for (int e = tid; e < 4096; e += 256){
                const int dd = e >> 7, c = e & 127;
                Ws[dd*132 + c] = W[(d0+dd)*DD + c];
            }
        } else {
            for (int e = tid; e < 4096; e += 256){
                const int c = e >> 5, dd = e & 31;
                Ws[dd*132 + c] = W[c*DD + d0 + dd];
            }
        }
        __syncthreads();

        #pragma unroll 4
        for (int dd = 0; dd < 32; dd++){
            const float4 w4 = *(const float4*)(Ws + dd*132 + 4*tx);
            const unsigned long long w0 = dup2(w4.x), w1 = dup2(w4.y),
                                     w2 = dup2(w4.z), w3 = dup2(w4.w);
            const float* er = Es + dd*102 + 2*ty;
            #pragma unroll
            for (int k = 0; k < 7; k++){
                const unsigned long long e2 = *(const unsigned long long*)(er + 16*k);
                ffma2(acc[k][0], e2, w0);
                ffma2(acc[k][1], e2, w1);
                ffma2(acc[k][2], e2, w2);
                ffma2(acc[k][3], e2, w3);
            }
        }
    }
    __syncthreads();

    float* dst = g_scr + (size_t)bb * TBLK
               + ((m==0) ? OFF_K : (m==1) ? OFF_Q : (m==2) ? OFF_V : OFF_P);
    float4 q1v = make_float4(0.f,0.f,0.f,0.f);
    if (m == 1) q1v = *(const float4*)(q1s + 4*tx);

    #pragma unroll
    for (int k = 0; k < 7; k++){
        const int n0 = 2*(ty + 8*k);
        if (n0 >= NN) continue;
        const int n1 = n0 + 1;
        float lo0,hi0,lo1,hi1,lo2,hi2,lo3,hi3;
        unpack2(acc[k][0], lo0, hi0);
        unpack2(acc[k][1], lo1, hi1);
        unpack2(acc[k][2], lo2, hi2);
        unpack2(acc[k][3], lo3, hi3);
        *(float4*)(dst + n0*132 + 4*tx) = make_float4(lo0+q1v.x, lo1+q1v.y, lo2+q1v.z, lo3+q1v.w);
        *(float4*)(dst + n1*132 + 4*tx) = make_float4(hi0+q1v.x, hi1+q1v.y, hi2+q1v.z, hi3+q1v.w);
    }
}

// =====================================================================
// decode: 128-thread CTA per batch; tables stream from L2; ~4KB smem
// => ~3.5 CTAs (14 warps)/SM for cross-batch latency hiding.
// Phases: A (8*act items) | C (c per thread, coalesced V rows) |
//         DE (j per thread, P row stream) | final. nw=4 barriers.
// =====================================================================
__global__ __launch_bounds__(128, 8) void decode_kernel(Args a, int c0, float* __restrict__ out)
{
    if (!g_ok || g_psel < 0) return;
    __shared__ __align__(16) float attw[800];
    __shared__ __align__(16) float mhb[128];
    __shared__ float candv[4];
    __shared__ int   candn[4], candj[4];
    __shared__ __align__(16) int idxs[104];
    __shared__ int   icur;

    const int bl = blockIdx.x;            // local chunk batch
    const int bg = c0 + bl;               // global batch
    const int tid = threadIdx.x;
    const int lane = tid & 31, wid = tid >> 5;
    const int klen = g_klen;
    const int* pre = (const int*)a.p[g_psel];

    const float* __restrict__ scrK = g_scr + (size_t)bl * TBLK + OFF_K;
    const float* __restrict__ scrV = g_scr + (size_t)bl * TBLK + OFF_V;
    const float* __restrict__ scrP = g_scr + (size_t)bl * TBLK + OFF_P;
    const float* __restrict__ scrQ = g_scr + (size_t)bl * TBLK + OFF_Q;

    // ---- init: visited scratch reuses attw; emit prefix; build active list ----
    {
        int* vis = (int*)attw;
        if (tid < NN) vis[tid] = 0;
        __syncthreads();
        if (tid < klen){
            int p = pre[bg*klen + tid];
            p = (p >= 0 && p < NN) ? p : 0;
            vis[p] = 1;
            out[bg*NN + tid] = (float)p;
        }
        __syncthreads();
        if (tid == 0){
            int m = 0;
            for (int n = 0; n < NN; n++) if (!vis[n]) idxs[m++] = n;
            int last = pre[bg*klen + (klen-1)];
            icur = (last >= 0 && last < NN) ? last : 0;
        }
        __syncthreads();
    }

    const int h = tid & 7;                // fixed head for phase A
    const int steps = NN - klen;
    for (int step = 0; step < steps; step++){
        const int act = steps - step;
        const int cur = icur;

        // ---- Phase A: att[h][j] = exp(q_h.K[idx[j]]_h / 4) ----
        {
            const float* Qrow = scrQ + cur*132 + h*16;   // L2 broadcast (16 thr/h)
            const ulonglong2 q0 = *(const ulonglong2*)(Qrow);
            const ulonglong2 q1 = *(const ulonglong2*)(Qrow + 4);
            const ulonglong2 q2 = *(const ulonglong2*)(Qrow + 8);
            const ulonglong2 q3 = *(const ulonglong2*)(Qrow + 12);
            for (int p = tid; p < 8*act; p += 128){      // p&7 == h invariant
                const int j = p >> 3;
                const float* Krow = scrK + idxs[j]*132 + h*16;
                const ulonglong2 k0 = *(const ulonglong2*)(Krow);
                const ulonglong2 k1 = *(const ulonglong2*)(Krow + 4);
                const ulonglong2 k2 = *(const ulonglong2*)(Krow + 8);
                const ulonglong2 k3 = *(const ulonglong2*)(Krow + 12);
                unsigned long long a0 = 0ull, a1 = 0ull;
                ffma2(a0, k0.x, q0.x); ffma2(a1, k0.y, q0.y);
                ffma2(a0, k1.x, q1.x); ffma2(a1, k1.y, q1.y);
                ffma2(a0, k2.x, q2.x); ffma2(a1, k2.y, q2.y);
                ffma2(a0, k3.x, q3.x); ffma2(a1, k3.y, q3.y);
                float s0,s1,s2,s3;
                unpack2(a0, s0, s1);
                unpack2(a1, s2, s3);
                attw[h*100 + j] = expf(((s0+s1) + (s2+s3)) * 0.25f);
            }
        }
        __syncthreads();

        // ---- Phase C: mh[c] = (sum_j w*V[idx[j]][c]) / (sum_j w); c = tid ----
        {
            const int c = tid;
            const float* ar = attw + (c >> 4)*100;
            const float* vbase = scrV + c;
            float accv = 0.f, accz = 0.f;
            int jj = 0;
            for (; jj + 4 <= act; jj += 4){
                const int4   i4 = *(const int4*)(idxs + jj);
                const float4 a4 = *(const float4*)(ar + jj);
                accv += a4.x * vbase[i4.x*132];  accz += a4.x;   // coalesced rows
                accv += a4.y * vbase[i4.y*132];  accz += a4.y;
                accv += a4.z * vbase[i4.z*132];  accz += a4.z;
                accv += a4.w * vbase[i4.w*132];  accz += a4.w;
            }
            for (; jj < act; jj++){
                const float av = ar[jj];
                accv += av * vbase[idxs[jj]*132];
                accz += av;
            }
            mhb[c] = accv / accz;
        }
        __syncthreads();

        // ---- Phase DE: sc = mh.P[node]; block argmax (node tie-break) ----
        {
            float best = NEG_INF; int bn = 1000 + tid, bj = 0;
            if (tid < act){
                const int node = idxs[tid];
                const float* Prow = scrP + node*132;    // MLP-32 stream
                unsigned long long a0 = 0ull, a1 = 0ull;
                #pragma unroll 8
                for (int q = 0; q < 32; q++){
                    const ulonglong2 pq = *(const ulonglong2*)(Prow + 4*q);  // LDG.128
                    const ulonglong2 mq = *(const ulonglong2*)(mhb + 4*q);   // LDS.128
                    ffma2(a0, mq.x, pq.x);
                    ffma2(a1, mq.y, pq.y);
                }
                float s0,s1,s2,s3;
                unpack2(a0, s0, s1);
                unpack2(a1, s2, s3);
                best = (s0+s1) + (s2+s3);   // tanh & 1/sqrt(d) monotone: skip
                bn = node; bj = tid;
            }
            #pragma unroll
            for (int o = 16; o; o >>= 1){
                const float ov = __shfl_xor_sync(0xffffffffu, best, o);
                const int   on = __shfl_xor_sync(0xffffffffu, bn,   o);
                const int   oj = __shfl_xor_sync(0xffffffffu, bj,   o);
                if (ov > best || (ov == best && on < bn)){ best = ov; bn = on; bj = oj; }
            }
            if (lane == 0){ candv[wid] = best; candn[wid] = bn; candj[wid] = bj; }
        }
        __syncthreads();

        // ---- final: reduce 4 candidates, swap-remove, emit ----
        if (tid == 0){
            float best = candv[0]; int bn = candn[0], bj = candj[0];
            #pragma unroll
            for (int w = 1; w < 4; w++){
                const float ov = candv[w];
                const int on = candn[w], oj = candj[w];
                if (ov > best || (ov == best && on < bn)){ best = ov; bn = on; bj = oj; }
            }
            idxs[bj] = idxs[act-1];
            icur = bn;
            out[bg*NN + klen + step] = (float)bn;
        }
        __syncthreads();
    }
}

// =====================================================================
extern "C" void kernel_launch(void* const* d_in, const int* in_sizes, int n_in,
                              void* d_out, int out_size)
{
    Args a;
    for (int i = 0; i < 10; i++){
        a.p[i]  = (i < n_in) ? d_in[i] : d_in[0];
        a.sz[i] = (i < n_in) ? (long)in_sizes[i] : 0;
    }
    a.n = (n_in < 10) ? n_in : 10;
    a.batch = out_size / NN;
    if (a.batch < 1) a.batch = 1;
    float* out = (float*)d_out;

    prep_kernel<<<1, 32>>>(a);
    prefill_kernel<<<a.batch, 128>>>(a, out);

    for (int c0 = 0; c0 < a.batch; c0 += CH){
        const int cb = (a.batch - c0 < CH) ? (a.batch - c0) : CH;
        dim3 g(cb, 4);
        gemm_kernel<<<g, 256>>>(a, c0);
        decode_kernel<<<cb, 128>>>(a, c0, out);
    }
}